// round 1
// baseline (speedup 1.0000x reference)
#include <cuda_runtime.h>
#include <math_constants.h>

// Shapes (fixed by the problem)
#define Bz 32
#define Cc 256
#define HW 1024
#define Nn 32768      // Bz * HW
#define Kk 1024
#define Dd 256
#define TOTAL_Z 8388608   // Nn * Dd

// Scratch (no allocations allowed)
__device__ float  g_Z[Nn];        // ||z_n||^2 (fp32, sequential)
__device__ float  g_B[Kk];        // ||c_k||^2
__device__ float  g_cbT[Dd * Kk]; // codebook transposed: [d][k]
__device__ int    g_idx[Nn];
__device__ double g_loss;

// ---- prep: codebook norms + transpose + zero loss ----
__global__ void prep_cb_kernel(const float* __restrict__ cb) {
    int k = blockIdx.x * blockDim.x + threadIdx.x;
    if (k == 0) g_loss = 0.0;
    if (k < Kk) {
        float s = 0.f;
        #pragma unroll 8
        for (int d = 0; d < Dd; d++) {
            float v = cb[k * Dd + d];
            s = __fadd_rn(s, __fmul_rn(v, v));   // square then add, no fma (match jnp)
            g_cbT[d * Kk + k] = v;
        }
        g_B[k] = s;
    }
}

// ---- prep: z norms (coalesced across hw for each channel) ----
__global__ void prep_z_kernel(const float* __restrict__ z) {
    int n = blockIdx.x * blockDim.x + threadIdx.x;   // exactly 32768 threads
    int b = n >> 10, hw = n & 1023;
    const float* p = z + (size_t)b * Cc * HW + hw;
    float s = 0.f;
    #pragma unroll 8
    for (int c = 0; c < Cc; c++) {
        float v = p[(size_t)c * HW];
        s = __fadd_rn(s, __fmul_rn(v, v));
    }
    g_Z[n] = s;
}

// ---- main: fused fp32 distance-GEMM + running argmin ----
// CTA: 64 rows (vectors) x all 1024 codes in 16 tiles of 64.
// smem: zs[256][64] (full-D z tile) + cs[256][64] (per-tile codebook slab) = 128 KB.
__global__ void __launch_bounds__(256, 1) argmin_kernel(const float* __restrict__ z) {
    extern __shared__ float sm[];
    float* zs = sm;               // [Dd][64], d-major
    float* cs = sm + Dd * 64;     // [Dd][64], d-major

    int tid = threadIdx.x;
    int n0  = blockIdx.x * 64;    // 64 | 1024, never crosses a batch boundary
    int b   = n0 >> 10;
    int hw0 = n0 & 1023;

    // Stage z tile: zs[d][i] = z[b, d, hw0+i]  (coalesced LDG, conflict-free STS)
    {
        int i  = tid & 63;
        int db = tid >> 6;        // 0..3
        const float* p = z + (size_t)b * Cc * HW + hw0 + i;
        #pragma unroll 16
        for (int r = 0; r < 64; r++) {
            int d = db + (r << 2);
            zs[d * 64 + i] = p[(size_t)d * HW];
        }
    }

    int tx = tid & 15, ty = tid >> 4;        // 16x16 thread grid, 4x4 micro-tile
    float Zr[4];
    #pragma unroll
    for (int ii = 0; ii < 4; ii++) Zr[ii] = g_Z[n0 + ty * 4 + ii];

    float bestv[4]; int besti[4];
    #pragma unroll
    for (int ii = 0; ii < 4; ii++) { bestv[ii] = CUDART_INF_F; besti[ii] = 0; }

    for (int kt = 0; kt < 16; kt++) {
        int k0 = kt * 64;
        __syncthreads();   // previous tile's compute done before overwriting cs
        // Stage codebook slab from transposed copy (coalesced float4)
        {
            int jq = tid & 15;    // float4 column
            int db = tid >> 4;    // 0..15
            #pragma unroll
            for (int r = 0; r < 16; r++) {
                int d = db + (r << 4);
                float4 v = *(const float4*)&g_cbT[d * Kk + k0 + jq * 4];
                *(float4*)&cs[d * 64 + jq * 4] = v;
            }
        }
        __syncthreads();

        float acc[4][4];
        #pragma unroll
        for (int ii = 0; ii < 4; ii++)
            #pragma unroll
            for (int jj = 0; jj < 4; jj++) acc[ii][jj] = 0.f;

        #pragma unroll 8
        for (int dd = 0; dd < Dd; dd++) {
            float4 a = *(const float4*)&zs[dd * 64 + ty * 4];
            float4 c = *(const float4*)&cs[dd * 64 + tx * 4];
            acc[0][0] = fmaf(a.x, c.x, acc[0][0]);
            acc[0][1] = fmaf(a.x, c.y, acc[0][1]);
            acc[0][2] = fmaf(a.x, c.z, acc[0][2]);
            acc[0][3] = fmaf(a.x, c.w, acc[0][3]);
            acc[1][0] = fmaf(a.y, c.x, acc[1][0]);
            acc[1][1] = fmaf(a.y, c.y, acc[1][1]);
            acc[1][2] = fmaf(a.y, c.z, acc[1][2]);
            acc[1][3] = fmaf(a.y, c.w, acc[1][3]);
            acc[2][0] = fmaf(a.z, c.x, acc[2][0]);
            acc[2][1] = fmaf(a.z, c.y, acc[2][1]);
            acc[2][2] = fmaf(a.z, c.z, acc[2][2]);
            acc[2][3] = fmaf(a.z, c.w, acc[2][3]);
            acc[3][0] = fmaf(a.w, c.x, acc[3][0]);
            acc[3][1] = fmaf(a.w, c.y, acc[3][1]);
            acc[3][2] = fmaf(a.w, c.z, acc[3][2]);
            acc[3][3] = fmaf(a.w, c.w, acc[3][3]);
        }

        // d = fl( fl(Z + B) - 2*dot )  — exact emulation of the reference's
        // final roundings (2*dot is exact; fma does the single final rounding).
        #pragma unroll
        for (int jj = 0; jj < 4; jj++) {
            int kk = k0 + tx * 4 + jj;
            float Bk = g_B[kk];
            #pragma unroll
            for (int ii = 0; ii < 4; ii++) {
                float dv = fmaf(-2.0f, acc[ii][jj], __fadd_rn(Zr[ii], Bk));
                if (dv < bestv[ii]) { bestv[ii] = dv; besti[ii] = kk; }
            }
        }
    }
    __syncthreads();

    // Cross-thread argmin reduce (first-index tie-break, matching jnp.argmin)
    float* rv = sm;                     // 64*16 floats
    int*   ri = (int*)(sm + 1024);      // 64*16 ints
    #pragma unroll
    for (int ii = 0; ii < 4; ii++) {
        int row = ty * 4 + ii;
        rv[row * 16 + tx] = bestv[ii];
        ri[row * 16 + tx] = besti[ii];
    }
    __syncthreads();
    if (tid < 64) {
        float v = CUDART_INF_F; int bi = 0x7fffffff;
        #pragma unroll
        for (int t = 0; t < 16; t++) {
            float vv = rv[tid * 16 + t];
            int   id = ri[tid * 16 + t];
            if (vv < v || (vv == v && id < bi)) { v = vv; bi = id; }
        }
        g_idx[n0 + tid] = bi;
    }
}

// ---- output: z_q_st (straight-through emulated) + loss accumulation ----
__global__ void output_kernel(const float* __restrict__ z,
                              const float* __restrict__ cb,
                              float* __restrict__ out) {
    int l = blockIdx.x * blockDim.x + threadIdx.x;   // exactly 8388608 threads
    int hw = l & 1023;
    int c  = (l >> 10) & 255;
    int bb = l >> 18;
    int n  = (bb << 10) + hw;
    int idx = g_idx[n];
    float zq = cb[idx * Dd + c];
    float zv = z[l];
    float diff = __fsub_rn(zq, zv);            // (z_q - z) in fp32, like jnp
    out[l] = __fadd_rn(zv, diff);              // z + (z_q - z)

    double sq = (double)diff * (double)diff;
    #pragma unroll
    for (int o = 16; o; o >>= 1) sq += __shfl_down_sync(0xffffffffu, sq, o);
    __shared__ double wsum[8];
    int lane = threadIdx.x & 31, w = threadIdx.x >> 5;
    if (lane == 0) wsum[w] = sq;
    __syncthreads();
    if (threadIdx.x == 0) {
        double t = 0.0;
        #pragma unroll
        for (int i = 0; i < 8; i++) t += wsum[i];
        atomicAdd(&g_loss, t);
    }
}

// ---- tail: vq_loss scalar + indices as float (guarded by out_size) ----
__global__ void tail_kernel(float* __restrict__ out, int out_size) {
    int n = blockIdx.x * blockDim.x + threadIdx.x;
    if (n < Nn && out_size >= TOTAL_Z + 1 + Nn)
        out[TOTAL_Z + 1 + n] = (float)g_idx[n];
    if (n == 0 && out_size > TOTAL_Z) {
        double mean = g_loss * (1.0 / (double)TOTAL_Z);
        float cl = (float)mean;
        out[TOTAL_Z] = __fadd_rn(cl, __fmul_rn(0.25f, cl));  // cb_loss + 0.25*commit
    }
}

extern "C" void kernel_launch(void* const* d_in, const int* in_sizes, int n_in,
                              void* d_out, int out_size) {
    const float* z  = (const float*)d_in[0];
    const float* cb = (const float*)d_in[1];
    float* out = (float*)d_out;

    const int smem = 2 * Dd * 64 * (int)sizeof(float);  // 128 KB
    cudaFuncSetAttribute(argmin_kernel,
                         cudaFuncAttributeMaxDynamicSharedMemorySize, smem);

    prep_cb_kernel<<<4, 256>>>(cb);
    prep_z_kernel<<<128, 256>>>(z);
    argmin_kernel<<<512, 256, smem>>>(z);
    output_kernel<<<32768, 256>>>(z, cb, out);
    tail_kernel<<<128, 256>>>(out, out_size);
}

// round 3
// speedup vs baseline: 1.4954x; 1.4954x over previous
#include <cuda_runtime.h>
#include <math_constants.h>

// Shapes (fixed by the problem)
#define Bz 32
#define Cc 256
#define HW 1024
#define Nn 32768      // Bz * HW
#define Kk 1024
#define Dd 256
#define TOTAL_Z 8388608   // Nn * Dd

// Scratch (no allocations allowed)
__device__ float  g_Z[Nn];        // ||z_n||^2
__device__ float  g_B[Kk];        // ||c_k||^2
__device__ float  g_cbT[Dd * Kk]; // codebook transposed: [d][k]
__device__ int    g_idx[Nn];
__device__ double g_loss;

// ---------- packed f32x2 helpers (bit-identical to two scalar fmaf) ----------
__device__ __forceinline__ void fma2(unsigned long long& d,
                                     unsigned long long a,
                                     unsigned long long b) {
    asm("fma.rn.f32x2 %0, %1, %2, %0;" : "+l"(d) : "l"(a), "l"(b));
}
__device__ __forceinline__ unsigned long long pack2(float x) {
    unsigned long long r; unsigned xi = __float_as_uint(x);
    asm("mov.b64 %0, {%1, %2};" : "=l"(r) : "r"(xi), "r"(xi));
    return r;
}
__device__ __forceinline__ void unpack2(unsigned long long v, float& lo, float& hi) {
    asm("mov.b64 {%0, %1}, %2;" : "=f"(lo), "=f"(hi) : "l"(v));
}

// ---- prep: codebook norms + transpose + zero loss ----
__global__ void prep_cb_kernel(const float* __restrict__ cb) {
    int k = blockIdx.x * blockDim.x + threadIdx.x;
    if (k == 0) g_loss = 0.0;
    if (k < Kk) {
        float s = 0.f;
        #pragma unroll 8
        for (int d = 0; d < Dd; d++) {
            float v = cb[k * Dd + d];
            s = __fadd_rn(s, __fmul_rn(v, v));
            g_cbT[d * Kk + k] = v;
        }
        g_B[k] = s;
    }
}

// ---- prep: z norms (coalesced across hw) ----
__global__ void prep_z_kernel(const float* __restrict__ z) {
    int n = blockIdx.x * blockDim.x + threadIdx.x;   // exactly 32768 threads
    int b = n >> 10, hw = n & 1023;
    const float* p = z + (size_t)b * Cc * HW + hw;
    float s = 0.f;
    #pragma unroll 8
    for (int c = 0; c < Cc; c++) {
        float v = p[(size_t)c * HW];
        s = __fadd_rn(s, __fmul_rn(v, v));
    }
    g_Z[n] = s;
}

// ================= main fused distance-GEMM + argmin ===================
// CTA: 128 rows (n) x 128 cols (k-tile), 8 k-tiles -> all 1024 codes.
// 256 threads, 8x8 micro-tile, packed f32x2 FMA.
// smem: zs[256][128] (full-D z tile, 128KB) + cs[2][64][128] (double-buffered
// codebook chunk, 64KB) = 192KB dynamic.
#define BM 128
#define BN 128
#define DCH 64

__device__ __forceinline__ void issue_chunk(float* cs, int tid, int p, int buf) {
    int kt = p >> 2, ch = p & 3;
    int dd = tid >> 2;          // 0..63
    int t4 = tid & 3;           // 0..3, each thread: 8 x 16B
    const float* src = g_cbT + (size_t)(ch * DCH + dd) * Kk + kt * BN;
    float* dst = cs + buf * (DCH * BN) + dd * BN;
    #pragma unroll
    for (int it = 0; it < 8; it++) {
        int col = (t4 + it * 4) * 4;
        unsigned saddr = (unsigned)__cvta_generic_to_shared(dst + col);
        asm volatile("cp.async.cg.shared.global [%0], [%1], 16;"
                     :: "r"(saddr), "l"(src + col));
    }
    asm volatile("cp.async.commit_group;");
}

__global__ void __launch_bounds__(256, 1) argmin_kernel(const float* __restrict__ z) {
    extern __shared__ float sm[];
    float* zs = sm;                  // [256][128]
    float* cs = sm + Dd * BM;        // [2][64][128]

    int tid = threadIdx.x;
    int n0  = blockIdx.x * BM;       // 128 | 1024: never crosses batch boundary
    int b   = n0 >> 10;
    int hw0 = n0 & 1023;

    // Stage full-D z tile: zs[d][i] = z[b, d, hw0+i] (coalesced float4)
    {
        int lane = tid & 31, wrp = tid >> 5;
        const float* zp = z + (size_t)b * Cc * HW + hw0 + lane * 4;
        #pragma unroll 8
        for (int d = wrp; d < Dd; d += 8)
            *(float4*)&zs[d * BM + lane * 4] = *(const float4*)(zp + (size_t)d * HW);
    }

    int tx = tid & 15, ty = tid >> 4;     // 16x16 thread grid, 8x8 micro-tile
    float Zr[8];
    #pragma unroll
    for (int i = 0; i < 8; i++) Zr[i] = g_Z[n0 + ty * 8 + i];

    float bestv[8]; int besti[8];
    #pragma unroll
    for (int i = 0; i < 8; i++) { bestv[i] = CUDART_INF_F; besti[i] = 0; }

    unsigned long long acc[8][4];    // 8 rows x 4 col-pairs

    int buf = 0;
    issue_chunk(cs, tid, 0, 0);

    for (int p = 0; p < 32; p++) {   // p = kt*4 + chunk
        int kt = p >> 2, ch = p & 3;
        asm volatile("cp.async.wait_group 0;" ::: "memory");
        __syncthreads();
        if (p < 31) issue_chunk(cs, tid, p + 1, buf ^ 1);

        if (ch == 0) {
            #pragma unroll
            for (int i = 0; i < 8; i++)
                #pragma unroll
                for (int j = 0; j < 4; j++) acc[i][j] = 0ull;
        }

        const float* zbase = zs + (ch * DCH) * BM + ty * 8;
        const float* cbase = cs + buf * (DCH * BN) + tx * 8;
        #pragma unroll 4
        for (int dd = 0; dd < DCH; dd++) {
            float4 a0 = *(const float4*)(zbase + dd * BM);
            float4 a1 = *(const float4*)(zbase + dd * BM + 4);
            ulonglong2 c0 = *(const ulonglong2*)(cbase + dd * BN);
            ulonglong2 c1 = *(const ulonglong2*)(cbase + dd * BN + 4);
            unsigned long long ap[8];
            ap[0] = pack2(a0.x); ap[1] = pack2(a0.y);
            ap[2] = pack2(a0.z); ap[3] = pack2(a0.w);
            ap[4] = pack2(a1.x); ap[5] = pack2(a1.y);
            ap[6] = pack2(a1.z); ap[7] = pack2(a1.w);
            #pragma unroll
            for (int i = 0; i < 8; i++) {
                fma2(acc[i][0], ap[i], c0.x);
                fma2(acc[i][1], ap[i], c0.y);
                fma2(acc[i][2], ap[i], c1.x);
                fma2(acc[i][3], ap[i], c1.y);
            }
        }

        if (ch == 3) {
            // d = fl( fl(Z + B) - 2*dot ): exact reference rounding emulation
            int k0 = kt * BN + tx * 8;
            #pragma unroll
            for (int j2 = 0; j2 < 4; j2++) {
                float Blo = g_B[k0 + j2 * 2];
                float Bhi = g_B[k0 + j2 * 2 + 1];
                #pragma unroll
                for (int i = 0; i < 8; i++) {
                    float dlo, dhi;
                    unpack2(acc[i][j2], dlo, dhi);
                    float v0 = fmaf(-2.0f, dlo, __fadd_rn(Zr[i], Blo));
                    float v1 = fmaf(-2.0f, dhi, __fadd_rn(Zr[i], Bhi));
                    if (v0 < bestv[i]) { bestv[i] = v0; besti[i] = k0 + j2 * 2; }
                    if (v1 < bestv[i]) { bestv[i] = v1; besti[i] = k0 + j2 * 2 + 1; }
                }
            }
        }
        buf ^= 1;
    }
    __syncthreads();

    // Cross-thread argmin reduce (first-index tie-break = jnp.argmin)
    float* rv = sm;                       // [128][16]
    int*   ri = (int*)(sm + BM * 16);     // [128][16]
    #pragma unroll
    for (int i = 0; i < 8; i++) {
        int row = ty * 8 + i;
        rv[row * 16 + tx] = bestv[i];
        ri[row * 16 + tx] = besti[i];
    }
    __syncthreads();
    if (tid < BM) {
        float v = CUDART_INF_F; int bi = 0x7fffffff;
        #pragma unroll
        for (int t = 0; t < 16; t++) {
            float vv = rv[tid * 16 + t];
            int   id = ri[tid * 16 + t];
            if (vv < v || (vv == v && id < bi)) { v = vv; bi = id; }
        }
        g_idx[n0 + tid] = bi;
    }
}

// ---- output: tiled gather for z_q_st + loss accumulation ----
// Block = 32 vectors (same b, consecutive hw) x 256 channels.
__global__ void output_kernel(const float* __restrict__ z,
                              const float* __restrict__ cb,
                              float* __restrict__ out) {
    __shared__ float cbrow[32][257];      // padded: conflict-free transposed read
    __shared__ double wsum[8];

    int tid = threadIdx.x;
    int n0 = blockIdx.x * 32;
    int b = n0 >> 10, hw0 = n0 & 1023;

    // Gather 32 codebook rows, coalesced (8 threads per row, float4)
    {
        int r = tid >> 3, q = tid & 3;
        // 8 threads/row -> each does 8 float4; use q over 0..7
        int q8 = tid & 7;
        int idx = g_idx[n0 + r];
        const float4* src = (const float4*)(cb + (size_t)idx * Dd);
        #pragma unroll
        for (int it = 0; it < 8; it++) {
            float4 v = src[q8 + it * 8];
            int c = (q8 + it * 8) * 4;
            cbrow[r][c]     = v.x;
            cbrow[r][c + 1] = v.y;
            cbrow[r][c + 2] = v.z;
            cbrow[r][c + 3] = v.w;
        }
        (void)q;
    }
    __syncthreads();

    int i = tid & 31, w = tid >> 5;       // lane over hw (coalesced), warp over c
    const float* zp = z   + (size_t)b * Cc * HW + hw0 + i;
    float*       op = out + (size_t)b * Cc * HW + hw0 + i;

    double accd = 0.0;
    #pragma unroll 8
    for (int c = w; c < Cc; c += 8) {
        float zv = zp[(size_t)c * HW];
        float zq = cbrow[i][c];
        float diff = __fsub_rn(zq, zv);
        op[(size_t)c * HW] = __fadd_rn(zv, diff);
        accd += (double)diff * (double)diff;
    }

    #pragma unroll
    for (int o = 16; o; o >>= 1) accd += __shfl_down_sync(0xffffffffu, accd, o);
    int lane = tid & 31;
    if (lane == 0) wsum[w] = accd;
    __syncthreads();
    if (tid == 0) {
        double t = 0.0;
        #pragma unroll
        for (int k = 0; k < 8; k++) t += wsum[k];
        atomicAdd(&g_loss, t);
    }
}

// ---- tail: vq_loss scalar + indices as float ----
__global__ void tail_kernel(float* __restrict__ out, int out_size) {
    int n = blockIdx.x * blockDim.x + threadIdx.x;
    if (n < Nn && out_size >= TOTAL_Z + 1 + Nn)
        out[TOTAL_Z + 1 + n] = (float)g_idx[n];
    if (n == 0 && out_size > TOTAL_Z) {
        double mean = g_loss * (1.0 / (double)TOTAL_Z);
        float cl = (float)mean;
        out[TOTAL_Z] = __fadd_rn(cl, __fmul_rn(0.25f, cl));
    }
}

extern "C" void kernel_launch(void* const* d_in, const int* in_sizes, int n_in,
                              void* d_out, int out_size) {
    const float* z  = (const float*)d_in[0];
    const float* cb = (const float*)d_in[1];
    float* out = (float*)d_out;

    const int smem = (Dd * BM + 2 * DCH * BN) * (int)sizeof(float);  // 192 KB
    cudaFuncSetAttribute(argmin_kernel,
                         cudaFuncAttributeMaxDynamicSharedMemorySize, smem);

    prep_cb_kernel<<<4, 256>>>(cb);
    prep_z_kernel<<<128, 256>>>(z);
    argmin_kernel<<<Nn / BM, 256, smem>>>(z);
    output_kernel<<<Nn / 32, 256>>>(z, cb, out);
    tail_kernel<<<128, 256>>>(out, out_size);
}

// round 5
// speedup vs baseline: 1.5476x; 1.0349x over previous
#include <cuda_runtime.h>
#include <math_constants.h>

// Shapes (fixed by the problem)
#define Bz 32
#define Cc 256
#define HW 1024
#define Nn 32768      // Bz * HW
#define Kk 1024
#define Dd 256
#define TOTAL_Z 8388608   // Nn * Dd

#define MARGIN 2e-3f
#define CAP 256

// Scratch (static __device__ arrays; no runtime allocation)
__device__ float  g_Z[Nn];          // ||z_n||^2 (sequential fp32, as in R1/R2)
__device__ float  g_B[Kk];          // ||c_k||^2 (sequential fp32, as in R1/R2)
__device__ float  g_ct[Kk * Dd];    // codebook rounded to tf32 (k-major)
__device__ float  g_dmat[(size_t)Nn * Kk]; // approx distances (134 MB)
__device__ int    g_idx[Nn];
__device__ double g_loss;

// ---- prep: codebook norms + tf32 copy + zero loss ----
__global__ void prep_cb_kernel(const float* __restrict__ cb) {
    int k = blockIdx.x * blockDim.x + threadIdx.x;
    if (k == 0) g_loss = 0.0;
    if (k < Kk) {
        float s = 0.f;
        #pragma unroll 8
        for (int d = 0; d < Dd; d++) {
            float v = cb[k * Dd + d];
            s = __fadd_rn(s, __fmul_rn(v, v));   // keep byte-identical to R2
            unsigned t;
            asm("cvt.rna.tf32.f32 %0, %1;" : "=r"(t) : "f"(v));
            ((unsigned*)g_ct)[k * Dd + d] = t;
        }
        g_B[k] = s;
    }
}

// ---- prep: z norms (coalesced across hw) ----
__global__ void prep_z_kernel(const float* __restrict__ z) {
    int n = blockIdx.x * blockDim.x + threadIdx.x;   // exactly 32768 threads
    int b = n >> 10, hw = n & 1023;
    const float* p = z + (size_t)b * Cc * HW + hw;
    float s = 0.f;
    #pragma unroll 8
    for (int c = 0; c < Cc; c++) {
        float v = p[(size_t)c * HW];
        s = __fadd_rn(s, __fmul_rn(v, v));
    }
    g_Z[n] = s;
}

// ================== TF32 tensor-core distance GEMM =====================
// CTA: 128 rows (n) x all 1024 codes; 256 threads = 8 warps (2m x 4n),
// warp tile 64m x 32n, mma m16n8k8 tf32.
// smem: zs[128][260] tf32 (full-D z tile) + cs[2][128][68] (codebook chunk,
// k-major, 64 d per chunk, double buffered).
#define ZPAD 260
#define CPAD 68

__device__ __forceinline__ void issue_chunk_tc(float* cs, int tid, int p, int buf) {
    int kt = p >> 2, dch = p & 3;
    int row  = tid >> 1;          // 0..127  (local k)
    int half = tid & 1;
    const float* src = g_ct + (size_t)(kt * 128 + row) * Dd + dch * 64 + half * 32;
    float* dst = cs + buf * (128 * CPAD) + row * CPAD + half * 32;
    #pragma unroll
    for (int i = 0; i < 8; i++) {
        unsigned saddr = (unsigned)__cvta_generic_to_shared(dst + i * 4);
        asm volatile("cp.async.cg.shared.global [%0], [%1], 16;"
                     :: "r"(saddr), "l"(src + i * 4));
    }
    asm volatile("cp.async.commit_group;");
}

__device__ __forceinline__ void mma_tf32(float c[4], const unsigned a[4],
                                         const unsigned b[2]) {
    asm volatile(
        "mma.sync.aligned.m16n8k8.row.col.f32.tf32.tf32.f32 "
        "{%0,%1,%2,%3},{%4,%5,%6,%7},{%8,%9},{%0,%1,%2,%3};"
        : "+f"(c[0]), "+f"(c[1]), "+f"(c[2]), "+f"(c[3])
        : "r"(a[0]), "r"(a[1]), "r"(a[2]), "r"(a[3]), "r"(b[0]), "r"(b[1]));
}

__global__ void __launch_bounds__(256, 1) gemm_kernel(const float* __restrict__ z) {
    extern __shared__ float sm[];
    float* zs = sm;                      // [128][ZPAD] (tf32 bits)
    float* cs = sm + 128 * ZPAD;         // [2][128][CPAD]

    int tid = threadIdx.x;
    int n0  = blockIdx.x * 128;
    int b   = n0 >> 10;
    int hw0 = n0 & 1023;

    // Stage z tile as tf32, n-major: zs[i][d] = tf32(z[b, d, hw0+i])
    {
        int i  = tid & 127;
        int dg = tid >> 7;               // 0..1
        const float* zp = z + (size_t)b * Cc * HW + hw0 + i;
        unsigned* zsu = (unsigned*)zs;
        #pragma unroll 8
        for (int d = dg; d < Dd; d += 2) {
            float v = zp[(size_t)d * HW];
            unsigned t;
            asm("cvt.rna.tf32.f32 %0, %1;" : "=r"(t) : "f"(v));
            zsu[i * ZPAD + d] = t;
        }
    }

    int w  = tid >> 5, lane = tid & 31;
    int wm = w & 1,    wn   = w >> 1;    // warp grid 2m x 4n
    int tq = lane >> 2, tr  = lane & 3;  // groupID, threadID-in-group

    // Z values for this thread's 8 output rows
    float zr[4][2];
    #pragma unroll
    for (int i = 0; i < 4; i++)
        #pragma unroll
        for (int h = 0; h < 2; h++)
            zr[i][h] = g_Z[n0 + wm * 64 + i * 16 + h * 8 + tq];

    float accf[4][4][4];
    const unsigned* zsu = (const unsigned*)zs;

    int buf = 0;
    issue_chunk_tc(cs, tid, 0, 0);

    for (int p = 0; p < 32; p++) {       // p = kt*4 + dch
        int kt = p >> 2, dch = p & 3;
        asm volatile("cp.async.wait_group 0;" ::: "memory");
        __syncthreads();
        if (p < 31) issue_chunk_tc(cs, tid, p + 1, buf ^ 1);

        if (dch == 0) {
            #pragma unroll
            for (int i = 0; i < 4; i++)
                #pragma unroll
                for (int j = 0; j < 4; j++)
                    #pragma unroll
                    for (int q = 0; q < 4; q++) accf[i][j][q] = 0.f;
        }

        const unsigned* cbuf = (const unsigned*)(cs + buf * (128 * CPAD));
        #pragma unroll
        for (int s = 0; s < 8; s++) {
            int d0 = dch * 64 + s * 8;
            unsigned a[4][4];
            #pragma unroll
            for (int i = 0; i < 4; i++) {
                int r = wm * 64 + i * 16 + tq;
                a[i][0] = zsu[r * ZPAD + d0 + tr];
                a[i][1] = zsu[(r + 8) * ZPAD + d0 + tr];
                a[i][2] = zsu[r * ZPAD + d0 + 4 + tr];
                a[i][3] = zsu[(r + 8) * ZPAD + d0 + 4 + tr];
            }
            unsigned bb[4][2];
            #pragma unroll
            for (int j = 0; j < 4; j++) {
                int krow = wn * 32 + j * 8 + tq;
                bb[j][0] = cbuf[krow * CPAD + s * 8 + tr];
                bb[j][1] = cbuf[krow * CPAD + s * 8 + 4 + tr];
            }
            #pragma unroll
            for (int i = 0; i < 4; i++)
                #pragma unroll
                for (int j = 0; j < 4; j++)
                    mma_tf32(accf[i][j], a[i], bb[j]);
        }

        if (dch == 3) {
            // approx d = fmaf(-2, dot, fl(Z+B)); store to g_dmat
            #pragma unroll
            for (int j = 0; j < 4; j++) {
                int k0 = kt * 128 + wn * 32 + j * 8 + 2 * tr;
                float2 Bv = *(const float2*)&g_B[k0];
                #pragma unroll
                for (int i = 0; i < 4; i++)
                    #pragma unroll
                    for (int h = 0; h < 2; h++) {
                        int row = n0 + wm * 64 + i * 16 + h * 8 + tq;
                        float zb0 = __fadd_rn(zr[i][h], Bv.x);
                        float zb1 = __fadd_rn(zr[i][h], Bv.y);
                        float2 dv;
                        dv.x = fmaf(-2.0f, accf[i][j][h * 2 + 0], zb0);
                        dv.y = fmaf(-2.0f, accf[i][j][h * 2 + 1], zb1);
                        *(float2*)&g_dmat[(size_t)row * Kk + k0] = dv;
                    }
            }
        }
        buf ^= 1;
    }
}

// ============ scan: threshold candidates + exact fp32 rescore ============
// CTA: 32 rows; 8 warps, each warp handles 4 rows.
__global__ void __launch_bounds__(256) scan_kernel(const float* __restrict__ z,
                                                   const float* __restrict__ cb) {
    __shared__ float zrow[32][257];
    __shared__ int   cand[8][CAP];

    int tid = threadIdx.x, lane = tid & 31, w = tid >> 5;
    int n0 = blockIdx.x * 32;
    int b = n0 >> 10, hw0 = n0 & 1023;

    // Stage the 32 z rows (exact fp32), transposed-coalesced
    {
        int i = tid & 31, c0 = tid >> 5;
        const float* zp = z + (size_t)b * Cc * HW + hw0 + i;
        #pragma unroll 8
        for (int c = c0; c < Cc; c += 8) zrow[i][c] = zp[(size_t)c * HW];
    }
    __syncthreads();

    for (int rr = 0; rr < 4; rr++) {
        int r = w * 4 + rr;
        int n = n0 + r;
        const float* drow = g_dmat + (size_t)n * Kk;

        // load this row's 1024 approx distances, track min
        float v[32];
        float mn = CUDART_INF_F;
        #pragma unroll
        for (int kc = 0; kc < 32; kc++) {
            v[kc] = drow[kc * 32 + lane];
            mn = fminf(mn, v[kc]);
        }
        #pragma unroll
        for (int o = 16; o; o >>= 1) mn = fminf(mn, __shfl_xor_sync(~0u, mn, o));
        float th = mn + MARGIN;

        // ordered candidate append (ascending k, deterministic)
        int base = 0;
        #pragma unroll
        for (int kc = 0; kc < 32; kc++) {
            bool hit = (v[kc] <= th);
            unsigned m = __ballot_sync(~0u, hit);
            if (hit) {
                int pos = base + __popc(m & ((1u << lane) - 1u));
                if (pos < CAP) cand[w][pos] = kc * 32 + lane;
            }
            base += __popc(m);
        }
        int cnt = base < CAP ? base : CAP;
        __syncwarp();

        // exact rescore: sequential ascending-d fma chain (identical to R2)
        float bv = CUDART_INF_F; int bk = 0x7fffffff;
        float Zn = g_Z[n];
        for (int ci = lane; ci < cnt; ci += 32) {
            int k = cand[w][ci];
            const float* crow = cb + (size_t)k * Dd;
            float acc = 0.f;
            #pragma unroll 8
            for (int d = 0; d < Dd; d++) acc = fmaf(zrow[r][d], crow[d], acc);
            float dv = fmaf(-2.0f, acc, __fadd_rn(Zn, g_B[k]));
            if (dv < bv || (dv == bv && k < bk)) { bv = dv; bk = k; }
        }
        #pragma unroll
        for (int o = 16; o; o >>= 1) {
            float ov = __shfl_xor_sync(~0u, bv, o);
            int   ok = __shfl_xor_sync(~0u, bk, o);
            if (ov < bv || (ov == bv && ok < bk)) { bv = ov; bk = ok; }
        }
        if (lane == 0) g_idx[n] = bk;
        __syncwarp();
    }
}

// ---- output: tiled gather for z_q_st + loss accumulation (unchanged) ----
__global__ void output_kernel(const float* __restrict__ z,
                              const float* __restrict__ cb,
                              float* __restrict__ out) {
    __shared__ float cbrow[32][257];
    __shared__ double wsum[8];

    int tid = threadIdx.x;
    int n0 = blockIdx.x * 32;
    int b = n0 >> 10, hw0 = n0 & 1023;

    {
        int r = tid >> 3;
        int q8 = tid & 7;
        int idx = g_idx[n0 + r];
        const float4* src = (const float4*)(cb + (size_t)idx * Dd);
        #pragma unroll
        for (int it = 0; it < 8; it++) {
            float4 vv = src[q8 + it * 8];
            int c = (q8 + it * 8) * 4;
            cbrow[r][c]     = vv.x;
            cbrow[r][c + 1] = vv.y;
            cbrow[r][c + 2] = vv.z;
            cbrow[r][c + 3] = vv.w;
        }
    }
    __syncthreads();

    int i = tid & 31, w = tid >> 5;
    const float* zp = z   + (size_t)b * Cc * HW + hw0 + i;
    float*       op = out + (size_t)b * Cc * HW + hw0 + i;

    double accd = 0.0;
    #pragma unroll 8
    for (int c = w; c < Cc; c += 8) {
        float zv = zp[(size_t)c * HW];
        float zq = cbrow[i][c];
        float diff = __fsub_rn(zq, zv);
        op[(size_t)c * HW] = __fadd_rn(zv, diff);
        accd += (double)diff * (double)diff;
    }

    #pragma unroll
    for (int o = 16; o; o >>= 1) accd += __shfl_down_sync(0xffffffffu, accd, o);
    int lane = tid & 31;
    if (lane == 0) wsum[w] = accd;
    __syncthreads();
    if (tid == 0) {
        double t = 0.0;
        #pragma unroll
        for (int k = 0; k < 8; k++) t += wsum[k];
        atomicAdd(&g_loss, t);
    }
}

// ---- tail: vq_loss scalar + indices as float ----
__global__ void tail_kernel(float* __restrict__ out, int out_size) {
    int n = blockIdx.x * blockDim.x + threadIdx.x;
    if (n < Nn && out_size >= TOTAL_Z + 1 + Nn)
        out[TOTAL_Z + 1 + n] = (float)g_idx[n];
    if (n == 0 && out_size > TOTAL_Z) {
        double mean = g_loss * (1.0 / (double)TOTAL_Z);
        float cl = (float)mean;
        out[TOTAL_Z] = __fadd_rn(cl, __fmul_rn(0.25f, cl));
    }
}

extern "C" void kernel_launch(void* const* d_in, const int* in_sizes, int n_in,
                              void* d_out, int out_size) {
    const float* z  = (const float*)d_in[0];
    const float* cb = (const float*)d_in[1];
    float* out = (float*)d_out;

    const int smem = (128 * ZPAD + 2 * 128 * CPAD) * (int)sizeof(float); // 202752 B
    cudaFuncSetAttribute(gemm_kernel,
                         cudaFuncAttributeMaxDynamicSharedMemorySize, smem);

    prep_cb_kernel<<<4, 256>>>(cb);
    prep_z_kernel<<<128, 256>>>(z);
    gemm_kernel<<<Nn / 128, 256, smem>>>(z);
    scan_kernel<<<Nn / 32, 256>>>(z, cb);
    output_kernel<<<Nn / 32, 256>>>(z, cb, out);
    tail_kernel<<<128, 256>>>(out, out_size);
}